// round 2
// baseline (speedup 1.0000x reference)
#include <cuda_runtime.h>

#define HDIM 64
#define TT 512
#define BTILE 16
#define NTHREADS 256
#define PAD 20

typedef unsigned long long ull;

struct Smem {
    float w0[64 * 256];    // [k][j*4+gate] <- w_hh0[(gate*64+j)*64+k]
    float wi1[64 * 256];   // same regroup of w_ih1
    float wh1[64 * 256];   // same regroup of w_hh1
    float hA[2][64 * PAD]; // layer-0 hidden, [buf][k*PAD + b]
    float hB[2][64 * PAD]; // layer-1 hidden
    float xs[2][BTILE * 4];
};

__device__ __forceinline__ ull pack2(float x, float y) {
    ull r;
    asm("mov.b64 %0, {%1, %2};" : "=l"(r) : "f"(x), "f"(y));
    return r;
}
__device__ __forceinline__ void unpack2(ull v, float& x, float& y) {
    asm("mov.b64 {%0, %1}, %2;" : "=f"(x), "=f"(y) : "l"(v));
}
__device__ __forceinline__ ull fma2(ull a, ull b, ull c) {
    ull d;
    asm("fma.rn.f32x2 %0, %1, %2, %3;" : "=l"(d) : "l"(a), "l"(b), "l"(c));
    return d;
}
__device__ __forceinline__ float sigf(float x) {
    return __fdividef(1.f, 1.f + __expf(-x));
}
__device__ __forceinline__ float tanhff(float x) {
    return __fdividef(2.f, 1.f + __expf(-2.f * x)) - 1.f;
}

// gate epilogue: activations + cell update, h written to smem, c stays in regs
__device__ __forceinline__ void cell_update(const ull aI[4], const ull aF[4],
                                            const ull aG[4], const ull aO[4],
                                            float c[8], float* __restrict__ hw) {
    float hn[8];
#pragma unroll
    for (int p = 0; p < 4; p++) {
        float gi0, gi1, gf0, gf1, gg0, gg1, go0, go1;
        unpack2(aI[p], gi0, gi1);
        unpack2(aF[p], gf0, gf1);
        unpack2(aG[p], gg0, gg1);
        unpack2(aO[p], go0, go1);
        float I0 = sigf(gi0), F0 = sigf(gf0), G0 = tanhff(gg0), O0 = sigf(go0);
        c[2 * p] = F0 * c[2 * p] + I0 * G0;
        hn[2 * p] = O0 * tanhff(c[2 * p]);
        float I1 = sigf(gi1), F1 = sigf(gf1), G1 = tanhff(gg1), O1 = sigf(go1);
        c[2 * p + 1] = F1 * c[2 * p + 1] + I1 * G1;
        hn[2 * p + 1] = O1 * tanhff(c[2 * p + 1]);
    }
    *(float4*)hw = make_float4(hn[0], hn[1], hn[2], hn[3]);
    *(float4*)(hw + 4) = make_float4(hn[4], hn[5], hn[6], hn[7]);
}

__global__ void __launch_bounds__(NTHREADS, 1)
lstm_fused_kernel(const float* __restrict__ x,
                  const float* __restrict__ w_ih0, const float* __restrict__ w_hh0,
                  const float* __restrict__ b_ih0, const float* __restrict__ b_hh0,
                  const float* __restrict__ w_ih1, const float* __restrict__ w_hh1,
                  const float* __restrict__ b_ih1, const float* __restrict__ b_hh1,
                  const float* __restrict__ fc_w, const float* __restrict__ fc_b,
                  float* __restrict__ out)
{
    extern __shared__ __align__(16) unsigned char smem_raw[];
    Smem& sh = *reinterpret_cast<Smem*>(smem_raw);
    const int tid = threadIdx.x;
    const int b0 = blockIdx.x * BTILE;

    // ---- stage recurrent weights, regrouped: [k][j*4+gate] ----
    for (int e = tid; e < 64 * 256; e += NTHREADS) {
        int row = e >> 6, k = e & 63;
        int gate = row >> 6, jj = row & 63;
        int d = k * 256 + jj * 4 + gate;
        sh.w0[d] = w_hh0[e];
        sh.wi1[d] = w_ih1[e];
        sh.wh1[d] = w_hh1[e];
    }
    // ---- zero h buffers ----
    for (int e = tid; e < 64 * PAD; e += NTHREADS) {
        sh.hA[0][e] = 0.f; sh.hA[1][e] = 0.f;
        sh.hB[0][e] = 0.f; sh.hB[1][e] = 0.f;
    }
    // ---- preload x for t=0 ----
    if (tid < BTILE)
        *(float4*)&sh.xs[0][tid * 4] = ((const float4*)x)[(size_t)(b0 + tid) * TT];

    const bool isG0 = (tid < 128);
    const int local = isG0 ? tid : tid - 128;
    const int j = local & 63;
    const int bh = local >> 6;

    float wi0[16], bias[4];
    if (isG0) {
#pragma unroll
        for (int g = 0; g < 4; g++) {
            float4 wv = *(const float4*)(w_ih0 + (g * 64 + j) * 4);
            wi0[g * 4 + 0] = wv.x; wi0[g * 4 + 1] = wv.y;
            wi0[g * 4 + 2] = wv.z; wi0[g * 4 + 3] = wv.w;
            bias[g] = b_ih0[g * 64 + j] + b_hh0[g * 64 + j];
        }
    } else {
#pragma unroll
        for (int g = 0; g < 4; g++) bias[g] = b_ih1[g * 64 + j] + b_hh1[g * 64 + j];
    }
    float c[8];
#pragma unroll
    for (int i = 0; i < 8; i++) c[i] = 0.f;

    __syncthreads();

    // ============ pipelined recurrence ============
    // round r: G0 computes layer-0 step t=r (r<512); G1 computes layer-1 step t=r-1 (r>=1)
    for (int r = 0; r <= TT; r++) {
        float4 xpre;
        const bool pre = (tid < BTILE) && (r <= TT - 2);
        if (pre) xpre = ((const float4*)x)[(size_t)(b0 + tid) * TT + (r + 1)];

        if (isG0) {
            if (r < TT) {
                const float* hr = sh.hA[r & 1] + bh * 8;
                const float* wp = sh.w0 + j * 4;
                const float4* xp = (const float4*)sh.xs[r & 1];
                ull aI[4], aF[4], aG[4], aO[4];
#pragma unroll
                for (int p = 0; p < 4; p++) {
                    float4 xa = xp[bh * 8 + 2 * p];
                    float4 xb = xp[bh * 8 + 2 * p + 1];
                    float s0[4], s1[4];
#pragma unroll
                    for (int g = 0; g < 4; g++) {
                        s0[g] = bias[g] + wi0[g*4]*xa.x + wi0[g*4+1]*xa.y
                                        + wi0[g*4+2]*xa.z + wi0[g*4+3]*xa.w;
                        s1[g] = bias[g] + wi0[g*4]*xb.x + wi0[g*4+1]*xb.y
                                        + wi0[g*4+2]*xb.z + wi0[g*4+3]*xb.w;
                    }
                    aI[p] = pack2(s0[0], s1[0]); aF[p] = pack2(s0[1], s1[1]);
                    aG[p] = pack2(s0[2], s1[2]); aO[p] = pack2(s0[3], s1[3]);
                }
#pragma unroll 8
                for (int k = 0; k < 64; k++) {
                    ulonglong2 ha = *(const ulonglong2*)(hr + k * PAD);
                    ulonglong2 hb = *(const ulonglong2*)(hr + k * PAD + 4);
                    float4 w = *(const float4*)(wp + (k << 8));
                    ull wI = pack2(w.x, w.x), wF = pack2(w.y, w.y);
                    ull wG = pack2(w.z, w.z), wO = pack2(w.w, w.w);
                    aI[0] = fma2(ha.x, wI, aI[0]); aI[1] = fma2(ha.y, wI, aI[1]);
                    aI[2] = fma2(hb.x, wI, aI[2]); aI[3] = fma2(hb.y, wI, aI[3]);
                    aF[0] = fma2(ha.x, wF, aF[0]); aF[1] = fma2(ha.y, wF, aF[1]);
                    aF[2] = fma2(hb.x, wF, aF[2]); aF[3] = fma2(hb.y, wF, aF[3]);
                    aG[0] = fma2(ha.x, wG, aG[0]); aG[1] = fma2(ha.y, wG, aG[1]);
                    aG[2] = fma2(hb.x, wG, aG[2]); aG[3] = fma2(hb.y, wG, aG[3]);
                    aO[0] = fma2(ha.x, wO, aO[0]); aO[1] = fma2(ha.y, wO, aO[1]);
                    aO[2] = fma2(hb.x, wO, aO[2]); aO[3] = fma2(hb.y, wO, aO[3]);
                }
                cell_update(aI, aF, aG, aO, c,
                            sh.hA[(r + 1) & 1] + j * PAD + bh * 8);
            }
        } else {
            if (r >= 1) {
                const float* ia = sh.hA[r & 1] + bh * 8; // layer-0 output h0_{r-1}
                const float* ib = sh.hB[r & 1] + bh * 8; // own state h1_{r-2}
                const float* wip = sh.wi1 + j * 4;
                const float* whp = sh.wh1 + j * 4;
                ull aI[4], aF[4], aG[4], aO[4];
#pragma unroll
                for (int p = 0; p < 4; p++) {
                    aI[p] = pack2(bias[0], bias[0]); aF[p] = pack2(bias[1], bias[1]);
                    aG[p] = pack2(bias[2], bias[2]); aO[p] = pack2(bias[3], bias[3]);
                }
#pragma unroll 4
                for (int k = 0; k < 64; k++) {
                    ulonglong2 xa = *(const ulonglong2*)(ia + k * PAD);
                    ulonglong2 xb = *(const ulonglong2*)(ia + k * PAD + 4);
                    float4 wi = *(const float4*)(wip + (k << 8));
                    ull wI = pack2(wi.x, wi.x), wF = pack2(wi.y, wi.y);
                    ull wG = pack2(wi.z, wi.z), wO = pack2(wi.w, wi.w);
                    aI[0] = fma2(xa.x, wI, aI[0]); aI[1] = fma2(xa.y, wI, aI[1]);
                    aI[2] = fma2(xb.x, wI, aI[2]); aI[3] = fma2(xb.y, wI, aI[3]);
                    aF[0] = fma2(xa.x, wF, aF[0]); aF[1] = fma2(xa.y, wF, aF[1]);
                    aF[2] = fma2(xb.x, wF, aF[2]); aF[3] = fma2(xb.y, wF, aF[3]);
                    aG[0] = fma2(xa.x, wG, aG[0]); aG[1] = fma2(xa.y, wG, aG[1]);
                    aG[2] = fma2(xb.x, wG, aG[2]); aG[3] = fma2(xb.y, wG, aG[3]);
                    aO[0] = fma2(xa.x, wO, aO[0]); aO[1] = fma2(xa.y, wO, aO[1]);
                    aO[2] = fma2(xb.x, wO, aO[2]); aO[3] = fma2(xb.y, wO, aO[3]);

                    ulonglong2 ya = *(const ulonglong2*)(ib + k * PAD);
                    ulonglong2 yb = *(const ulonglong2*)(ib + k * PAD + 4);
                    float4 wh = *(const float4*)(whp + (k << 8));
                    ull vI = pack2(wh.x, wh.x), vF = pack2(wh.y, wh.y);
                    ull vG = pack2(wh.z, wh.z), vO = pack2(wh.w, wh.w);
                    aI[0] = fma2(ya.x, vI, aI[0]); aI[1] = fma2(ya.y, vI, aI[1]);
                    aI[2] = fma2(yb.x, vI, aI[2]); aI[3] = fma2(yb.y, vI, aI[3]);
                    aF[0] = fma2(ya.x, vF, aF[0]); aF[1] = fma2(ya.y, vF, aF[1]);
                    aF[2] = fma2(yb.x, vF, aF[2]); aF[3] = fma2(yb.y, vF, aF[3]);
                    aG[0] = fma2(ya.x, vG, aG[0]); aG[1] = fma2(ya.y, vG, aG[1]);
                    aG[2] = fma2(yb.x, vG, aG[2]); aG[3] = fma2(yb.y, vG, aG[3]);
                    aO[0] = fma2(ya.x, vO, aO[0]); aO[1] = fma2(ya.y, vO, aO[1]);
                    aO[2] = fma2(yb.x, vO, aO[2]); aO[3] = fma2(yb.y, vO, aO[3]);
                }
                cell_update(aI, aF, aG, aO, c,
                            sh.hB[(r + 1) & 1] + j * PAD + bh * 8);
            }
        }

        if (pre) *(float4*)&sh.xs[(r + 1) & 1][tid * 4] = xpre;
        __syncthreads();
    }

    // ============ FC + tanh epilogue ============
    // h_n (layer 1, t=511) sits in hB[(TT+1)&1] = hB[1], layout [k][b].
    for (int e = tid; e < 4096; e += NTHREADS) {
        int jj = e >> 6, k = e & 63;
        sh.w0[k * 64 + jj] = fc_w[e]; // transpose: [k][j]
    }
    __syncthreads();

    const int q = tid >> 6;       // quarter: 4 batch rows each
    const int jo = tid & 63;
    const float* hfin = sh.hB[(TT + 1) & 1];
    float fb = fc_b[jo];
    float acc[4];
#pragma unroll
    for (int m = 0; m < 4; m++) acc[m] = fb;
#pragma unroll 8
    for (int k = 0; k < 64; k++) {
        float w = sh.w0[k * 64 + jo];
#pragma unroll
        for (int m = 0; m < 4; m++) acc[m] += w * hfin[k * PAD + q * 4 + m];
    }
#pragma unroll
    for (int m = 0; m < 4; m++)
        out[(size_t)(b0 + q * 4 + m) * 64 + jo] = tanhff(acc[m]);
}

extern "C" void kernel_launch(void* const* d_in, const int* in_sizes, int n_in,
                              void* d_out, int out_size) {
    const float* x     = (const float*)d_in[0];
    const float* w_ih0 = (const float*)d_in[1];
    const float* w_hh0 = (const float*)d_in[2];
    const float* b_ih0 = (const float*)d_in[3];
    const float* b_hh0 = (const float*)d_in[4];
    const float* w_ih1 = (const float*)d_in[5];
    const float* w_hh1 = (const float*)d_in[6];
    const float* b_ih1 = (const float*)d_in[7];
    const float* b_hh1 = (const float*)d_in[8];
    const float* fc_w  = (const float*)d_in[9];
    const float* fc_b  = (const float*)d_in[10];
    float* out = (float*)d_out;

    const int smem = (int)sizeof(Smem);
    cudaFuncSetAttribute(lstm_fused_kernel,
                         cudaFuncAttributeMaxDynamicSharedMemorySize, smem);
    lstm_fused_kernel<<<2048 / BTILE, NTHREADS, smem>>>(
        x, w_ih0, w_hh0, b_ih0, b_hh0,
        w_ih1, w_hh1, b_ih1, b_hh1, fc_w, fc_b, out);
}